// round 15
// baseline (speedup 1.0000x reference)
#include <cuda_runtime.h>
#include <cuda_fp16.h>
#include <cstdint>

#define NR 65536
#define HID 1024
#define COUT 37
#define EPSV 1e-5f
#define KP2 2240         // folded K: 2048 feat + 36 dist + 128 pos + 28 pad

// GEMM1: block 128x128, BK=64, 8 warps of 32x64, ldmatrix, mbarrier+counter 3-slot pipeline, 2 CTA/SM
#define G1_BM 128
#define G1_BN 128
#define G1_BK 64
#define G1_STRIDE 144                     // 128B data + 16B pad per k-row
#define G1_ASZ (G1_BM * G1_STRIDE)        // 18432
#define G1_BSZ (G1_BN * G1_STRIDE)        // 18432
#define G1_STAGE (G1_ASZ + G1_BSZ)        // 36864
#define G1_MBAR_OFF (3 * G1_STAGE)        // 110592: full mbars at +0/8/16, counters at +24/28/32
#define G1_STATS_OFF (G1_MBAR_OFF + 64)   // 110656
#define SMEM_G1 (G1_STATS_OFF + 1024)     // 111680  (x2 CTA = 223360 <= 228KB)
#define G1_NIT (KP2 / G1_BK)              // 35

// GEMM2: block 128x64, BK=32, 8 warps of 32x32, 2 CTA/SM
#define STAGE2_B 15360
#define SMEM_G2 (8192 + 3 * STAGE2_B)

#define BN4_BLOCKS 264

// ---- scratch (static device globals; no allocation) ----
__device__ __half g_X[(size_t)NR * KP2];
__device__ __half g_Y[(size_t)NR * HID];
__device__ __half g_W1t[(size_t)HID * KP2];   // W1' [n][k] fp16 (embed folded via M36)
__device__ __half g_W2t[(size_t)64 * HID];    // W2 [n][k] fp16, zero-padded n
__device__ float g_bn4_part[BN4_BLOCKS][8];
__device__ float g_bn4_scale[4];
__device__ float g_bn4_shift[4];
__device__ float g_colsum[HID];
__device__ float g_colsq[HID];

__device__ __forceinline__ uint32_t smem_u32(const void* p) {
    uint32_t a;
    asm("{ .reg .u64 t; cvta.to.shared.u64 t, %1; cvt.u32.u64 %0, t; }" : "=r"(a) : "l"(p));
    return a;
}
__device__ __forceinline__ void cpa16(uint32_t dst, const void* src) {
    asm volatile("cp.async.cg.shared.global [%0], [%1], 16;" :: "r"(dst), "l"(src));
}
__device__ __forceinline__ void cpa_commit() {
    asm volatile("cp.async.commit_group;" ::: "memory");
}
__device__ __forceinline__ void cpa_wait1() {
    asm volatile("cp.async.wait_group 1;" ::: "memory");
}
__device__ __forceinline__ void ldsm4(uint32_t* r, uint32_t addr) {
    asm volatile("ldmatrix.sync.aligned.m8n8.x4.shared.b16 {%0,%1,%2,%3}, [%4];"
                 : "=r"(r[0]), "=r"(r[1]), "=r"(r[2]), "=r"(r[3]) : "r"(addr));
}
__device__ __forceinline__ void mma16816(float* c, const uint32_t* a, uint32_t b0, uint32_t b1) {
    asm volatile(
        "mma.sync.aligned.m16n8k16.row.col.f32.f16.f16.f32 "
        "{%0,%1,%2,%3}, {%4,%5,%6,%7}, {%8,%9}, {%0,%1,%2,%3};"
        : "+f"(c[0]), "+f"(c[1]), "+f"(c[2]), "+f"(c[3])
        : "r"(a[0]), "r"(a[1]), "r"(a[2]), "r"(a[3]), "r"(b0), "r"(b1));
}

// ---- mbarrier primitives (full barriers only) ----
__device__ __forceinline__ void mbar_init(uint32_t a, uint32_t cnt) {
    asm volatile("mbarrier.init.shared.b64 [%0], %1;" :: "r"(a), "r"(cnt) : "memory");
}
// .noinc: async arrive consumes one expected arrival; HW flips the barrier as
// soon as data lands, off the warps' critical path.
__device__ __forceinline__ void cpa_mbar_arrive(uint32_t a) {
    asm volatile("cp.async.mbarrier.arrive.noinc.shared.b64 [%0];" :: "r"(a) : "memory");
}
__device__ __forceinline__ void mbar_wait_acq(uint32_t a, int parity) {
    asm volatile(
        "{\n\t.reg .pred P1;\n\t"
        "WL_%=:\n\t"
        "mbarrier.try_wait.parity.acquire.cta.shared::cta.b64 P1, [%0], %1, 0x989680;\n\t"
        "@P1 bra.uni WD_%=;\n\t"
        "bra.uni WL_%=;\n\t"
        "WD_%=:\n\t}"
        :: "r"(a), "r"(parity) : "memory");
}

// ---- smem counter barrier (empty side): cheap fast path vs TRYWAIT 90 cyc ----
__device__ __forceinline__ void cnt_add(uint32_t addr) {
    asm volatile("red.release.cta.shared.add.u32 [%0], 1;" :: "r"(addr) : "memory");
}
__device__ __forceinline__ void cnt_wait(uint32_t addr, uint32_t need) {
    uint32_t v;
    do {
        asm volatile("ld.acquire.cta.shared.u32 %0, [%1];" : "=r"(v) : "r"(addr) : "memory");
    } while ((int)(v - need) < 0);
}

// ============ k_bn4_reduce: per-block partial sums (no init needed) ================
__global__ __launch_bounds__(256) void k_bn4_reduce(const float* __restrict__ boxes) {
    float s[4] = {0, 0, 0, 0}, q[4] = {0, 0, 0, 0};
    for (int i = blockIdx.x * 256 + threadIdx.x; i < NR; i += BN4_BLOCKS * 256) {
        const float* b = boxes + (size_t)i * 5;
        float x1 = b[1], y1 = b[2], x2 = b[3], y2 = b[4];
        float w = x2 - x1, h = y2 - y1;
        float v0 = x1 + 0.5f * w, v1 = y1 + 0.5f * h;
        s[0] += v0; s[1] += v1; s[2] += w; s[3] += h;
        q[0] += v0 * v0; q[1] += v1 * v1; q[2] += w * w; q[3] += h * h;
    }
    #pragma unroll
    for (int o = 16; o; o >>= 1) {
        #pragma unroll
        for (int j = 0; j < 4; j++) {
            s[j] += __shfl_down_sync(0xFFFFFFFFu, s[j], o);
            q[j] += __shfl_down_sync(0xFFFFFFFFu, q[j], o);
        }
    }
    __shared__ float sm[8][8];
    int warp = threadIdx.x >> 5, lane = threadIdx.x & 31;
    if (lane == 0) {
        #pragma unroll
        for (int j = 0; j < 4; j++) { sm[warp][j] = s[j]; sm[warp][4 + j] = q[j]; }
    }
    __syncthreads();
    if (threadIdx.x < 8) {
        float a = 0.f;
        #pragma unroll
        for (int w2 = 0; w2 < 8; w2++) a += sm[w2][threadIdx.x];
        g_bn4_part[blockIdx.x][threadIdx.x] = a;
    }
}

__global__ void k_bn4_fin(const float* __restrict__ g4, const float* __restrict__ b4) {
    int t = threadIdx.x;
    __shared__ float acc[8][8];
    int j = t & 7, ch = t >> 3;
    float a = 0.f;
    for (int i = ch; i < BN4_BLOCKS; i += 8) a += g_bn4_part[i][j];
    acc[ch][j] = a;
    __syncthreads();
    if (t < 4) {
        float ms = 0.f, qs = 0.f;
        #pragma unroll
        for (int c = 0; c < 8; c++) { ms += acc[c][t]; qs += acc[c][t + 4]; }
        float m = ms / (float)NR;
        float v = qs / (float)NR - m * m;
        float sc = g4[t] * rsqrtf(v + EPSV);
        g_bn4_scale[t] = sc;
        g_bn4_shift[t] = b4[t] - m * sc;
    }
}

// ============ k_pre: fused prep (feat cvt + W1 transpose + M36 + W2 + init + embed) =
#define RB_TR 4096
#define RB_M36 6272
#define RB_INIT 6304
#define RB_W2 6305
#define RB_EMB 6561
#define PRE_GRID (RB_EMB + NR / 8)

__global__ __launch_bounds__(256) void k_pre(
    const float* __restrict__ feat, const float* __restrict__ w1,
    const float* __restrict__ objW, const float* __restrict__ w2,
    const float* __restrict__ dist, const float* __restrict__ boxes,
    const float* __restrict__ posW, const float* __restrict__ posB) {
    int b = blockIdx.x, t = threadIdx.x;
    if (b < RB_TR) {
        for (size_t cid = (size_t)b * 256 + t; cid < (size_t)NR * 256; cid += (size_t)RB_TR * 256) {
            size_t row = cid >> 8;
            int c = (int)(cid & 255);
            const float4* s = (const float4*)(feat + row * 2048 + c * 8);
            float4 v0 = s[0], v1 = s[1];
            __half2 h0 = __floats2half2_rn(v0.x, v0.y);
            __half2 h1 = __floats2half2_rn(v0.z, v0.w);
            __half2 h2 = __floats2half2_rn(v1.x, v1.y);
            __half2 h3 = __floats2half2_rn(v1.z, v1.w);
            uint4 u;
            u.x = *(uint32_t*)&h0; u.y = *(uint32_t*)&h1;
            u.z = *(uint32_t*)&h2; u.w = *(uint32_t*)&h3;
            *(uint4*)(g_X + row * KP2 + c * 8) = u;
        }
    } else if (b < RB_M36) {
        __shared__ float sm[32][33];
        int tile = b - RB_TR;
        int kt = tile % 68, nt = tile / 68;
        int n0 = nt * 32;
        int k0 = (kt < 64) ? kt * 32 : 2248 + (kt - 64) * 32;
        int dk0 = (kt < 64) ? kt * 32 : 2084 + (kt - 64) * 32;
        int tx = t & 31, tyb = t >> 5;
        #pragma unroll
        for (int p = 0; p < 4; p++) {
            int ty = tyb + p * 8;
            sm[ty][tx] = w1[(size_t)(k0 + ty) * HID + n0 + tx];
        }
        __syncthreads();
        #pragma unroll
        for (int p = 0; p < 4; p++) {
            int ty = tyb + p * 8;
            g_W1t[(size_t)(n0 + ty) * KP2 + dk0 + tx] = __float2half(sm[tx][ty]);
        }
    } else if (b < RB_INIT) {
        int n = (b - RB_M36) * 32 + (t & 31);
        for (int j = t >> 5; j < 36; j += 8) {
            float acc = 0.f;
            for (int p = 0; p < 200; p++)
                acc += __ldg(&objW[j * 200 + p]) * __ldg(&w1[(size_t)(2048 + p) * HID + n]);
            g_W1t[(size_t)n * KP2 + 2048 + j] = __float2half(acc);
        }
        for (int k = 2212 + (t >> 5); k < KP2; k += 8)
            g_W1t[(size_t)n * KP2 + k] = __float2half(0.f);
    } else if (b == RB_INIT) {
        for (int i = t; i < HID; i += 256) { g_colsum[i] = 0.f; g_colsq[i] = 0.f; }
    } else if (b < RB_EMB) {
        int idx = (b - RB_W2) * 256 + t;
        int n = idx >> 10, k = idx & 1023;
        g_W2t[idx] = __float2half(n < COUT ? w2[(size_t)k * COUT + n] : 0.f);
    } else {
        int warp = t >> 5, lane = t & 31;
        size_t row = (size_t)(b - RB_EMB) * 8 + warp;
        __half* xr = g_X + row * KP2;
        for (int j = lane; j < 36; j += 32)
            xr[2048 + j] = __float2half(dist[row * 36 + j]);
        const float* bx = boxes + row * 5;
        float x1 = __ldg(bx + 1), y1 = __ldg(bx + 2), x2 = __ldg(bx + 3), y2 = __ldg(bx + 4);
        float w = x2 - x1, h = y2 - y1;
        float s4[4] = {x1 + 0.5f * w, y1 + 0.5f * h, w, h};
        #pragma unroll
        for (int j = 0; j < 4; j++) s4[j] = s4[j] * g_bn4_scale[j] + g_bn4_shift[j];
        for (int c = lane; c < 128; c += 32) {
            float acc = __ldg(&posB[c]);
            #pragma unroll
            for (int k = 0; k < 4; k++) acc += s4[k] * __ldg(&posW[k * 128 + c]);
            xr[2084 + c] = __float2half(fmaxf(acc, 0.f));
        }
        for (int c = lane; c < KP2 - 2212; c += 32) xr[2212 + c] = __float2half(0.f);
    }
}

// ============ GEMM1: Y = X @ W1t', 128x128 blocks, 2 CTA/SM =========================
// Full side: HW cp.async.mbarrier.arrive.noinc (256 expected). Empty side: smem
// counter (+8 per slot consumption) with red.release / ld.acquire spin — fast path
// ~30 cyc vs 90 for mbarrier TRYWAIT. Refill hoisted mid-compute (R14).
__device__ __forceinline__ void g1_load(uint32_t sbase, int slot, const __half* Ag,
                                        const __half* Bg, int chunk, int t) {
    int k0 = chunk * G1_BK;
    uint32_t aB = sbase + slot * G1_STAGE;
    uint32_t bB = aB + G1_ASZ;
    #pragma unroll
    for (int i = 0; i < 4; i++) {
        int idx = t + i * 256;
        int r = idx >> 3, c = idx & 7;
        cpa16(aB + r * G1_STRIDE + c * 16, Ag + (size_t)r * KP2 + k0 + c * 8);
    }
    #pragma unroll
    for (int i = 0; i < 4; i++) {
        int idx = t + i * 256;
        int r = idx >> 3, c = idx & 7;
        cpa16(bB + r * G1_STRIDE + c * 16, Bg + (size_t)r * KP2 + k0 + c * 8);
    }
}

template <int KK0, int KK1>
__device__ __forceinline__ void g1_compute_half(uint32_t st, uint32_t aOff, uint32_t bOff,
                                                float acc[2][8][4]) {
    #pragma unroll
    for (int kk = KK0; kk < KK1; kk++) {
        uint32_t a[2][4], b[4][4];
        #pragma unroll
        for (int mt = 0; mt < 2; mt++)
            ldsm4(a[mt], st + aOff + mt * (16 * G1_STRIDE) + kk * 32);
        #pragma unroll
        for (int ng = 0; ng < 4; ng++)
            ldsm4(b[ng], st + bOff + ng * (16 * G1_STRIDE) + kk * 32);
        #pragma unroll
        for (int mt = 0; mt < 2; mt++)
            #pragma unroll
            for (int s = 0; s < 8; s++)
                mma16816(acc[mt][s], a[mt], b[s >> 1][(s & 1) * 2], b[s >> 1][(s & 1) * 2 + 1]);
    }
}

// one pipeline step: slot S computed (iter IT); slot SP=(S+2)%3 refilled with chunk IT+2
#define G1_STEP(S, SP, IT, PF, NE_SP) do {                                  \
    mbar_wait_acq(mb + (S) * 8, PF); PF ^= 1;                               \
    g1_compute_half<0, 2>(sbase + (S) * G1_STAGE, aOff, bOff, acc);         \
    if ((IT) >= 1 && (IT) + 2 < G1_NIT) {                                   \
        cnt_wait(cnt + (SP) * 4, NE_SP); NE_SP += 8;                        \
        g1_load(sbase, (SP), Ag, Bg, (IT) + 2, t);                          \
        cpa_mbar_arrive(mb + (SP) * 8);                                     \
    }                                                                       \
    g1_compute_half<2, 4>(sbase + (S) * G1_STAGE, aOff, bOff, acc);         \
    if (lane == 0) cnt_add(cnt + (S) * 4);                                  \
} while (0)

__global__ __launch_bounds__(256, 2) void k_gemm1() {
    extern __shared__ char sm1[];
    uint32_t sbase = smem_u32(sm1);
    uint32_t mb = sbase + G1_MBAR_OFF;      // full[s] at mb+8s
    uint32_t cnt = mb + 24;                 // counters[s] at cnt+4s
    int t = threadIdx.x, warp = t >> 5, lane = t & 31;
    int wr = warp >> 1, wc = warp & 1;      // 4x2 warps, warp tile 32x64
    int g = lane >> 2, tg = lane & 3;
    const size_t rowBase = (size_t)blockIdx.y * G1_BM;
    const int colBase = blockIdx.x * G1_BN;
    const __half* Ag = g_X + rowBase * KP2;
    const __half* Bg = g_W1t + (size_t)colBase * KP2;

    if (t == 0) {
        #pragma unroll
        for (int s = 0; s < 3; s++) {
            mbar_init(mb + s * 8, 256);        // full: per-thread cp.async arrives
            asm volatile("st.shared.u32 [%0], 0;" :: "r"(cnt + s * 4) : "memory");
        }
    }
    __syncthreads();

    float acc[2][8][4];
    #pragma unroll
    for (int i = 0; i < 2; i++)
        #pragma unroll
        for (int j = 0; j < 8; j++)
            #pragma unroll
            for (int c = 0; c < 4; c++) acc[i][j][c] = 0.f;

    const uint32_t aOff = (uint32_t)((wr * 32 + (lane & 15)) * G1_STRIDE + ((lane >> 4) << 4));
    const uint32_t bOff = (uint32_t)(G1_ASZ +
        (wc * 64 + (lane & 7) + ((lane >> 4) << 3)) * G1_STRIDE + (((lane >> 3) & 1) << 4));

    // prologue: fill all 3 slots
    g1_load(sbase, 0, Ag, Bg, 0, t); cpa_mbar_arrive(mb + 0);
    g1_load(sbase, 1, Ag, Bg, 1, t); cpa_mbar_arrive(mb + 8);
    g1_load(sbase, 2, Ag, Bg, 2, t); cpa_mbar_arrive(mb + 16);

    int pf0 = 0, pf1 = 0, pf2 = 0;
    uint32_t ne0 = 8, ne1 = 8, ne2 = 8;     // first refill of each slot needs 8 consumptions
    int it = 0;
    #pragma unroll 1
    for (int blk = 0; blk < 11; blk++) {     // iterations 0..32
        G1_STEP(0, 2, it, pf0, ne2);
        G1_STEP(1, 0, it + 1, pf1, ne0);
        G1_STEP(2, 1, it + 2, pf2, ne1);
        it += 3;
    }
    G1_STEP(0, 2, 33, pf0, ne2);              // tail: iters 33, 34 (no refills)
    G1_STEP(1, 0, 34, pf1, ne0);

    // ---- epilogue: Y fp16 + fused BN1 column stats (dedicated smem region) ----
    float* s_sum = (float*)(sm1 + G1_STATS_OFF);
    float* s_sq = s_sum + 128;
    if (t < 128) { s_sum[t] = 0.f; s_sq[t] = 0.f; }

    #pragma unroll
    for (int mt = 0; mt < 2; mt++) {
        size_t r0 = rowBase + wr * 32 + mt * 16 + g;
        #pragma unroll
        for (int s = 0; s < 8; s++) {
            int cc = colBase + wc * 64 + s * 8 + 2 * tg;
            __half2 h0 = __floats2half2_rn(acc[mt][s][0], acc[mt][s][1]);
            __half2 h1 = __floats2half2_rn(acc[mt][s][2], acc[mt][s][3]);
            *(__half2*)(g_Y + r0 * HID + cc) = h0;
            *(__half2*)(g_Y + (r0 + 8) * HID + cc) = h1;
        }
    }
    __syncthreads();   // zeros visible; all warps past mainloop

    #pragma unroll
    for (int s = 0; s < 8; s++) {
        #pragma unroll
        for (int j = 0; j < 2; j++) {
            float v0 = acc[0][s][j], v1 = acc[0][s][j + 2];
            float v2 = acc[1][s][j], v3 = acc[1][s][j + 2];
            float sv = v0 + v1 + v2 + v3;
            float qv = v0 * v0 + v1 * v1 + v2 * v2 + v3 * v3;
            #pragma unroll
            for (int o = 4; o < 32; o <<= 1) {
                sv += __shfl_xor_sync(0xFFFFFFFFu, sv, o);
                qv += __shfl_xor_sync(0xFFFFFFFFu, qv, o);
            }
            if (g == 0) {
                int cl = wc * 64 + s * 8 + 2 * tg + j;
                atomicAdd(&s_sum[cl], sv);
                atomicAdd(&s_sq[cl], qv);
            }
        }
    }
    __syncthreads();
    if (t < 128) {
        atomicAdd(&g_colsum[colBase + t], s_sum[t]);
        atomicAdd(&g_colsq[colBase + t], s_sq[t]);
    }
}

// ---- GEMM2: out = relu(BN(Y)) @ W2 + b2, 2 CTA/SM; BN1 finalize fused in prologue --
__device__ __forceinline__ uint32_t bn_h2(uint32_t raw, float2 sc, float2 sh) {
    __half2 h = *(__half2*)&raw;
    float2 f = __half22float2(h);
    f.x = fmaxf(f.x * sc.x + sh.x, 0.f);
    f.y = fmaxf(f.y * sc.y + sh.y, 0.f);
    __half2 o = __floats2half2_rn(f.x, f.y);
    return *(uint32_t*)&o;
}

__device__ __forceinline__ void g2_load(uint32_t sbase, int s, const __half* Ag,
                                        int chunk, int t) {
    int k0 = chunk * 32;
    uint32_t aB = sbase + 8192 + s * STAGE2_B;
    uint32_t bB = aB + 10240;
    #pragma unroll
    for (int i = 0; i < 2; i++) {
        int idx = t + i * 256;
        int r = idx >> 2, c = idx & 3;
        cpa16(aB + r * 80 + c * 16, Ag + (size_t)r * HID + k0 + c * 8);
    }
    {
        int r = t >> 2, c = t & 3;
        cpa16(bB + r * 80 + c * 16, g_W2t + (size_t)r * HID + k0 + c * 8);
    }
}

__global__ __launch_bounds__(256, 2) void k_gemm2(const float* __restrict__ bn1g,
                                                  const float* __restrict__ bn1b,
                                                  const float* __restrict__ b2,
                                                  float* __restrict__ out) {
    extern __shared__ char sm2[];
    float* s_scale = (float*)sm2;
    float* s_shift = s_scale + 1024;
    uint32_t sbase = smem_u32(sm2);
    int t = threadIdx.x;
    int warp = t >> 5, lane = t & 31;
    int wr = warp >> 1, wc = warp & 1;
    int g = lane >> 2, tg = lane & 3;
    const size_t rowBase = (size_t)blockIdx.y * 128;
    const __half* Ag = g_Y + rowBase * HID;

    // fused BN1 finalize: scale/shift from column stats
    #pragma unroll
    for (int i = t; i < 1024; i += 256) {
        float m = g_colsum[i] / (float)NR;
        float v = g_colsq[i] / (float)NR - m * m;
        float sc = __ldg(&bn1g[i]) * rsqrtf(v + EPSV);
        s_scale[i] = sc;
        s_shift[i] = __ldg(&bn1b[i]) - m * sc;
    }

    float acc[2][4][4];
    #pragma unroll
    for (int i = 0; i < 2; i++)
        #pragma unroll
        for (int j = 0; j < 4; j++)
            #pragma unroll
            for (int c = 0; c < 4; c++) acc[i][j][c] = 0.f;

    g2_load(sbase, 0, Ag, 0, t); cpa_commit();
    g2_load(sbase, 1, Ag, 1, t); cpa_commit();

    const int NIT = HID / 32;
    for (int it = 0; it < NIT; ++it) {
        cpa_wait1();
        __syncthreads();
        if (it + 2 < NIT) g2_load(sbase, (it + 2) % 3, Ag, it + 2, t);
        cpa_commit();

        const char* aS = sm2 + 8192 + (it % 3) * STAGE2_B;
        const char* bS = aS + 10240;
        #pragma unroll
        for (int kk = 0; kk < 2; kk++) {
            int kloc = kk * 16 + 2 * tg;
            int kglob = it * 32 + kloc;
            float2 sc0 = *(float2*)(s_scale + kglob);
            float2 sh0 = *(float2*)(s_shift + kglob);
            float2 sc1 = *(float2*)(s_scale + kglob + 8);
            float2 sh1 = *(float2*)(s_shift + kglob + 8);
            int kb = kloc * 2;
            uint32_t a[2][4];
            #pragma unroll
            for (int rt = 0; rt < 2; rt++) {
                int r0 = wr * 32 + rt * 16 + g;
                a[rt][0] = bn_h2(*(const uint32_t*)(aS + r0 * 80 + kb), sc0, sh0);
                a[rt][1] = bn_h2(*(const uint32_t*)(aS + (r0 + 8) * 80 + kb), sc0, sh0);
                a[rt][2] = bn_h2(*(const uint32_t*)(aS + r0 * 80 + kb + 16), sc1, sh1);
                a[rt][3] = bn_h2(*(const uint32_t*)(aS + (r0 + 8) * 80 + kb + 16), sc1, sh1);
            }
            #pragma unroll
            for (int s = 0; s < 4; s++) {
                int n = wc * 32 + s * 8 + g;
                uint32_t b0 = *(const uint32_t*)(bS + n * 80 + kb);
                uint32_t b1 = *(const uint32_t*)(bS + n * 80 + kb + 16);
                mma16816(acc[0][s], a[0], b0, b1);
                mma16816(acc[1][s], a[1], b0, b1);
            }
        }
    }

    #pragma unroll
    for (int rt = 0; rt < 2; rt++) {
        size_t r0 = rowBase + wr * 32 + rt * 16 + g;
        #pragma unroll
        for (int s = 0; s < 4; s++) {
            int cc = wc * 32 + s * 8 + 2 * tg;
            if (cc < COUT) {
                float bb = __ldg(&b2[cc]);
                out[r0 * COUT + cc] = acc[rt][s][0] + bb;
                out[(r0 + 8) * COUT + cc] = acc[rt][s][2] + bb;
            }
            if (cc + 1 < COUT) {
                float bb = __ldg(&b2[cc + 1]);
                out[r0 * COUT + cc + 1] = acc[rt][s][1] + bb;
                out[(r0 + 8) * COUT + cc + 1] = acc[rt][s][3] + bb;
            }
        }
    }
}

extern "C" void kernel_launch(void* const* d_in, const int* in_sizes, int n_in,
                              void* d_out, int out_size) {
    const float* dist  = (const float*)d_in[0];
    const float* boxes = (const float*)d_in[1];
    const float* feat  = (const float*)d_in[2];
    const float* objW  = (const float*)d_in[3];
    const float* bn4g  = (const float*)d_in[4];
    const float* bn4b  = (const float*)d_in[5];
    const float* posW  = (const float*)d_in[6];
    const float* posB  = (const float*)d_in[7];
    const float* w1    = (const float*)d_in[8];
    // d_in[9] = dec_b1: cancels inside BatchNorm, unused
    const float* bn1g  = (const float*)d_in[10];
    const float* bn1b  = (const float*)d_in[11];
    const float* w2    = (const float*)d_in[12];
    const float* b2    = (const float*)d_in[13];
    float* out = (float*)d_out;

    cudaFuncSetAttribute(k_gemm1, cudaFuncAttributeMaxDynamicSharedMemorySize, SMEM_G1);
    cudaFuncSetAttribute(k_gemm2, cudaFuncAttributeMaxDynamicSharedMemorySize, SMEM_G2);

    k_bn4_reduce<<<BN4_BLOCKS, 256>>>(boxes);
    k_bn4_fin<<<1, 64>>>(bn4g, bn4b);
    k_pre<<<PRE_GRID, 256>>>(feat, w1, objW, w2, dist, boxes, posW, posB);
    k_gemm1<<<dim3(HID / G1_BN, NR / G1_BM), 256, SMEM_G1>>>();   // 4th launch -> ncu capture
    k_gemm2<<<dim3(1, NR / 128), 256, SMEM_G2>>>(bn1g, bn1b, b2, out);
}

// round 16
// speedup vs baseline: 1.0326x; 1.0326x over previous
#include <cuda_runtime.h>
#include <cuda_fp16.h>
#include <cstdint>

#define NR 65536
#define HID 1024
#define COUT 37
#define EPSV 1e-5f
#define KP2 2240         // folded K: 2048 feat + 36 dist + 128 pos + 28 pad

// GEMM1: block 128x128, BK=64, 8 warps of 32x64, ldmatrix, mbarrier 3-slot pipeline, 2 CTA/SM
#define G1_BM 128
#define G1_BN 128
#define G1_BK 64
#define G1_STRIDE 144                     // 128B data + 16B pad per k-row
#define G1_ASZ (G1_BM * G1_STRIDE)        // 18432
#define G1_BSZ (G1_BN * G1_STRIDE)        // 18432
#define G1_STAGE (G1_ASZ + G1_BSZ)        // 36864
#define G1_MBAR_OFF (3 * G1_STAGE)        // 110592
#define G1_STATS_OFF (G1_MBAR_OFF + 64)   // 110656
#define SMEM_G1 (G1_STATS_OFF + 1024)     // 111680  (x2 CTA = 223360 <= 228KB)
#define G1_NIT (KP2 / G1_BK)              // 35

// GEMM2: block 128x64, BK=32, 8 warps of 32x32, 2 CTA/SM
#define STAGE2_B 15360
#define SMEM_G2 (8192 + 3 * STAGE2_B)

#define BN4_BLOCKS 264

// ---- scratch (static device globals; no allocation) ----
__device__ __half g_X[(size_t)NR * KP2];
__device__ __half g_Y[(size_t)NR * HID];
__device__ __half g_W1t[(size_t)HID * KP2];   // W1' [n][k] fp16 (embed folded via M36)
__device__ __half g_W2t[(size_t)64 * HID];    // W2 [n][k] fp16, zero-padded n
__device__ float g_bn4_part[BN4_BLOCKS][8];
__device__ float g_bn4_scale[4];
__device__ float g_bn4_shift[4];
__device__ float g_colsum[HID];
__device__ float g_colsq[HID];

__device__ __forceinline__ uint32_t smem_u32(const void* p) {
    uint32_t a;
    asm("{ .reg .u64 t; cvta.to.shared.u64 t, %1; cvt.u32.u64 %0, t; }" : "=r"(a) : "l"(p));
    return a;
}
__device__ __forceinline__ void cpa16(uint32_t dst, const void* src) {
    asm volatile("cp.async.cg.shared.global [%0], [%1], 16;" :: "r"(dst), "l"(src));
}
__device__ __forceinline__ void cpa_commit() {
    asm volatile("cp.async.commit_group;" ::: "memory");
}
__device__ __forceinline__ void cpa_wait1() {
    asm volatile("cp.async.wait_group 1;" ::: "memory");
}
__device__ __forceinline__ void ldsm4(uint32_t* r, uint32_t addr) {
    asm volatile("ldmatrix.sync.aligned.m8n8.x4.shared.b16 {%0,%1,%2,%3}, [%4];"
                 : "=r"(r[0]), "=r"(r[1]), "=r"(r[2]), "=r"(r[3]) : "r"(addr));
}
__device__ __forceinline__ void mma16816(float* c, const uint32_t* a, uint32_t b0, uint32_t b1) {
    asm volatile(
        "mma.sync.aligned.m16n8k16.row.col.f32.f16.f16.f32 "
        "{%0,%1,%2,%3}, {%4,%5,%6,%7}, {%8,%9}, {%0,%1,%2,%3};"
        : "+f"(c[0]), "+f"(c[1]), "+f"(c[2]), "+f"(c[3])
        : "r"(a[0]), "r"(a[1]), "r"(a[2]), "r"(a[3]), "r"(b0), "r"(b1));
}

// ---- mbarrier primitives ----
__device__ __forceinline__ void mbar_init(uint32_t a, uint32_t cnt) {
    asm volatile("mbarrier.init.shared.b64 [%0], %1;" :: "r"(a), "r"(cnt) : "memory");
}
__device__ __forceinline__ void mbar_arrive(uint32_t a) {
    asm volatile("mbarrier.arrive.shared.b64 _, [%0];" :: "r"(a) : "memory");
}
// .noinc: async arrive consumes one expected arrival; HW flips the barrier as
// soon as data lands, off the warps' critical path (R13 lesson).
// R15 lesson: mbarrier TRYWAIT is already the cheap multi-consumer wait; a
// hand-rolled ld.acquire spin loop is slower.
__device__ __forceinline__ void cpa_mbar_arrive(uint32_t a) {
    asm volatile("cp.async.mbarrier.arrive.noinc.shared.b64 [%0];" :: "r"(a) : "memory");
}
__device__ __forceinline__ void mbar_wait_acq(uint32_t a, int parity) {
    asm volatile(
        "{\n\t.reg .pred P1;\n\t"
        "WL_%=:\n\t"
        "mbarrier.try_wait.parity.acquire.cta.shared::cta.b64 P1, [%0], %1, 0x989680;\n\t"
        "@P1 bra.uni WD_%=;\n\t"
        "bra.uni WL_%=;\n\t"
        "WD_%=:\n\t}"
        :: "r"(a), "r"(parity) : "memory");
}
// relaxed wait: producer-side only (post-wait smem accesses are cp.async = async proxy)
__device__ __forceinline__ void mbar_wait_rlx(uint32_t a, int parity) {
    asm volatile(
        "{\n\t.reg .pred P1;\n\t"
        "WL_%=:\n\t"
        "mbarrier.try_wait.parity.relaxed.cta.shared::cta.b64 P1, [%0], %1, 0x989680;\n\t"
        "@P1 bra.uni WD_%=;\n\t"
        "bra.uni WL_%=;\n\t"
        "WD_%=:\n\t}"
        :: "r"(a), "r"(parity) : "memory");
}

// ============ k_bn4_reduce: per-block partial sums (no init needed) ================
__global__ __launch_bounds__(256) void k_bn4_reduce(const float* __restrict__ boxes) {
    float s[4] = {0, 0, 0, 0}, q[4] = {0, 0, 0, 0};
    for (int i = blockIdx.x * 256 + threadIdx.x; i < NR; i += BN4_BLOCKS * 256) {
        const float* b = boxes + (size_t)i * 5;
        float x1 = b[1], y1 = b[2], x2 = b[3], y2 = b[4];
        float w = x2 - x1, h = y2 - y1;
        float v0 = x1 + 0.5f * w, v1 = y1 + 0.5f * h;
        s[0] += v0; s[1] += v1; s[2] += w; s[3] += h;
        q[0] += v0 * v0; q[1] += v1 * v1; q[2] += w * w; q[3] += h * h;
    }
    #pragma unroll
    for (int o = 16; o; o >>= 1) {
        #pragma unroll
        for (int j = 0; j < 4; j++) {
            s[j] += __shfl_down_sync(0xFFFFFFFFu, s[j], o);
            q[j] += __shfl_down_sync(0xFFFFFFFFu, q[j], o);
        }
    }
    __shared__ float sm[8][8];
    int warp = threadIdx.x >> 5, lane = threadIdx.x & 31;
    if (lane == 0) {
        #pragma unroll
        for (int j = 0; j < 4; j++) { sm[warp][j] = s[j]; sm[warp][4 + j] = q[j]; }
    }
    __syncthreads();
    if (threadIdx.x < 8) {
        float a = 0.f;
        #pragma unroll
        for (int w2 = 0; w2 < 8; w2++) a += sm[w2][threadIdx.x];
        g_bn4_part[blockIdx.x][threadIdx.x] = a;
    }
}

__global__ void k_bn4_fin(const float* __restrict__ g4, const float* __restrict__ b4) {
    int t = threadIdx.x;
    __shared__ float acc[8][8];
    int j = t & 7, ch = t >> 3;
    float a = 0.f;
    for (int i = ch; i < BN4_BLOCKS; i += 8) a += g_bn4_part[i][j];
    acc[ch][j] = a;
    __syncthreads();
    if (t < 4) {
        float ms = 0.f, qs = 0.f;
        #pragma unroll
        for (int c = 0; c < 8; c++) { ms += acc[c][t]; qs += acc[c][t + 4]; }
        float m = ms / (float)NR;
        float v = qs / (float)NR - m * m;
        float sc = g4[t] * rsqrtf(v + EPSV);
        g_bn4_scale[t] = sc;
        g_bn4_shift[t] = b4[t] - m * sc;
    }
}

// ============ k_pre: fused prep (feat cvt + W1 transpose + M36 + W2 + init + embed) =
#define RB_TR 4096
#define RB_M36 6272
#define RB_INIT 6304
#define RB_W2 6305
#define RB_EMB 6561
#define PRE_GRID (RB_EMB + NR / 8)

__global__ __launch_bounds__(256) void k_pre(
    const float* __restrict__ feat, const float* __restrict__ w1,
    const float* __restrict__ objW, const float* __restrict__ w2,
    const float* __restrict__ dist, const float* __restrict__ boxes,
    const float* __restrict__ posW, const float* __restrict__ posB) {
    int b = blockIdx.x, t = threadIdx.x;
    if (b < RB_TR) {
        for (size_t cid = (size_t)b * 256 + t; cid < (size_t)NR * 256; cid += (size_t)RB_TR * 256) {
            size_t row = cid >> 8;
            int c = (int)(cid & 255);
            const float4* s = (const float4*)(feat + row * 2048 + c * 8);
            float4 v0 = s[0], v1 = s[1];
            __half2 h0 = __floats2half2_rn(v0.x, v0.y);
            __half2 h1 = __floats2half2_rn(v0.z, v0.w);
            __half2 h2 = __floats2half2_rn(v1.x, v1.y);
            __half2 h3 = __floats2half2_rn(v1.z, v1.w);
            uint4 u;
            u.x = *(uint32_t*)&h0; u.y = *(uint32_t*)&h1;
            u.z = *(uint32_t*)&h2; u.w = *(uint32_t*)&h3;
            *(uint4*)(g_X + row * KP2 + c * 8) = u;
        }
    } else if (b < RB_M36) {
        __shared__ float sm[32][33];
        int tile = b - RB_TR;
        int kt = tile % 68, nt = tile / 68;
        int n0 = nt * 32;
        int k0 = (kt < 64) ? kt * 32 : 2248 + (kt - 64) * 32;
        int dk0 = (kt < 64) ? kt * 32 : 2084 + (kt - 64) * 32;
        int tx = t & 31, tyb = t >> 5;
        #pragma unroll
        for (int p = 0; p < 4; p++) {
            int ty = tyb + p * 8;
            sm[ty][tx] = w1[(size_t)(k0 + ty) * HID + n0 + tx];
        }
        __syncthreads();
        #pragma unroll
        for (int p = 0; p < 4; p++) {
            int ty = tyb + p * 8;
            g_W1t[(size_t)(n0 + ty) * KP2 + dk0 + tx] = __float2half(sm[tx][ty]);
        }
    } else if (b < RB_INIT) {
        int n = (b - RB_M36) * 32 + (t & 31);
        for (int j = t >> 5; j < 36; j += 8) {
            float acc = 0.f;
            for (int p = 0; p < 200; p++)
                acc += __ldg(&objW[j * 200 + p]) * __ldg(&w1[(size_t)(2048 + p) * HID + n]);
            g_W1t[(size_t)n * KP2 + 2048 + j] = __float2half(acc);
        }
        for (int k = 2212 + (t >> 5); k < KP2; k += 8)
            g_W1t[(size_t)n * KP2 + k] = __float2half(0.f);
    } else if (b == RB_INIT) {
        for (int i = t; i < HID; i += 256) { g_colsum[i] = 0.f; g_colsq[i] = 0.f; }
    } else if (b < RB_EMB) {
        int idx = (b - RB_W2) * 256 + t;
        int n = idx >> 10, k = idx & 1023;
        g_W2t[idx] = __float2half(n < COUT ? w2[(size_t)k * COUT + n] : 0.f);
    } else {
        int warp = t >> 5, lane = t & 31;
        size_t row = (size_t)(b - RB_EMB) * 8 + warp;
        __half* xr = g_X + row * KP2;
        for (int j = lane; j < 36; j += 32)
            xr[2048 + j] = __float2half(dist[row * 36 + j]);
        const float* bx = boxes + row * 5;
        float x1 = __ldg(bx + 1), y1 = __ldg(bx + 2), x2 = __ldg(bx + 3), y2 = __ldg(bx + 4);
        float w = x2 - x1, h = y2 - y1;
        float s4[4] = {x1 + 0.5f * w, y1 + 0.5f * h, w, h};
        #pragma unroll
        for (int j = 0; j < 4; j++) s4[j] = s4[j] * g_bn4_scale[j] + g_bn4_shift[j];
        for (int c = lane; c < 128; c += 32) {
            float acc = __ldg(&posB[c]);
            #pragma unroll
            for (int k = 0; k < 4; k++) acc += s4[k] * __ldg(&posW[k * 128 + c]);
            xr[2084 + c] = __float2half(fmaxf(acc, 0.f));
        }
        for (int c = lane; c < KP2 - 2212; c += 32) xr[2212 + c] = __float2half(0.f);
    }
}

// ============ GEMM1: Y = X @ W1t', 128x128 blocks, mbarrier pipeline, 2 CTA/SM =====
// R14 protocol: HW async arrives on full (256 expected), lane-0 arrives on empty (8
// expected), refill hoisted into the middle of compute so the empty-wait + cp.async
// issue hide behind the second half of the mma work.
__device__ __forceinline__ void g1_load(uint32_t sbase, int slot, const __half* Ag,
                                        const __half* Bg, int chunk, int t) {
    int k0 = chunk * G1_BK;
    uint32_t aB = sbase + slot * G1_STAGE;
    uint32_t bB = aB + G1_ASZ;
    #pragma unroll
    for (int i = 0; i < 4; i++) {
        int idx = t + i * 256;
        int r = idx >> 3, c = idx & 7;
        cpa16(aB + r * G1_STRIDE + c * 16, Ag + (size_t)r * KP2 + k0 + c * 8);
    }
    #pragma unroll
    for (int i = 0; i < 4; i++) {
        int idx = t + i * 256;
        int r = idx >> 3, c = idx & 7;
        cpa16(bB + r * G1_STRIDE + c * 16, Bg + (size_t)r * KP2 + k0 + c * 8);
    }
}

template <int KK0, int KK1>
__device__ __forceinline__ void g1_compute_half(uint32_t st, uint32_t aOff, uint32_t bOff,
                                                float acc[2][8][4]) {
    #pragma unroll
    for (int kk = KK0; kk < KK1; kk++) {
        uint32_t a[2][4], b[4][4];
        #pragma unroll
        for (int mt = 0; mt < 2; mt++)
            ldsm4(a[mt], st + aOff + mt * (16 * G1_STRIDE) + kk * 32);
        #pragma unroll
        for (int ng = 0; ng < 4; ng++)
            ldsm4(b[ng], st + bOff + ng * (16 * G1_STRIDE) + kk * 32);
        #pragma unroll
        for (int mt = 0; mt < 2; mt++)
            #pragma unroll
            for (int s = 0; s < 8; s++)
                mma16816(acc[mt][s], a[mt], b[s >> 1][(s & 1) * 2], b[s >> 1][(s & 1) * 2 + 1]);
    }
}

// one pipeline step: slot S computed (iter IT); slot SP=(S+2)%3 refilled with chunk IT+2
#define G1_STEP(S, SP, IT, PF, PE_SP) do {                                  \
    mbar_wait_acq(mb + (S) * 8, PF); PF ^= 1;                               \
    g1_compute_half<0, 2>(sbase + (S) * G1_STAGE, aOff, bOff, acc);         \
    if ((IT) >= 1 && (IT) + 2 < G1_NIT) {                                   \
        mbar_wait_rlx(mb + 24 + (SP) * 8, PE_SP); PE_SP ^= 1;               \
        g1_load(sbase, (SP), Ag, Bg, (IT) + 2, t);                          \
        cpa_mbar_arrive(mb + (SP) * 8);                                     \
    }                                                                       \
    g1_compute_half<2, 4>(sbase + (S) * G1_STAGE, aOff, bOff, acc);         \
    if (lane == 0) mbar_arrive(mb + 24 + (S) * 8);                          \
} while (0)

__global__ __launch_bounds__(256, 2) void k_gemm1() {
    extern __shared__ char sm1[];
    uint32_t sbase = smem_u32(sm1);
    uint32_t mb = sbase + G1_MBAR_OFF;     // full[s] at mb+8s, empty[s] at mb+24+8s
    int t = threadIdx.x, warp = t >> 5, lane = t & 31;
    int wr = warp >> 1, wc = warp & 1;      // 4x2 warps, warp tile 32x64
    int g = lane >> 2, tg = lane & 3;
    const size_t rowBase = (size_t)blockIdx.y * G1_BM;
    const int colBase = blockIdx.x * G1_BN;
    const __half* Ag = g_X + rowBase * KP2;
    const __half* Bg = g_W1t + (size_t)colBase * KP2;

    if (t == 0) {
        #pragma unroll
        for (int s = 0; s < 3; s++) {
            mbar_init(mb + s * 8, 256);        // full: per-thread cp.async arrives
            mbar_init(mb + 24 + s * 8, 8);     // empty: one arrive per warp
        }
    }
    __syncthreads();

    float acc[2][8][4];
    #pragma unroll
    for (int i = 0; i < 2; i++)
        #pragma unroll
        for (int j = 0; j < 8; j++)
            #pragma unroll
            for (int c = 0; c < 4; c++) acc[i][j][c] = 0.f;

    const uint32_t aOff = (uint32_t)((wr * 32 + (lane & 15)) * G1_STRIDE + ((lane >> 4) << 4));
    const uint32_t bOff = (uint32_t)(G1_ASZ +
        (wc * 64 + (lane & 7) + ((lane >> 4) << 3)) * G1_STRIDE + (((lane >> 3) & 1) << 4));

    // prologue: fill all 3 slots
    g1_load(sbase, 0, Ag, Bg, 0, t); cpa_mbar_arrive(mb + 0);
    g1_load(sbase, 1, Ag, Bg, 1, t); cpa_mbar_arrive(mb + 8);
    g1_load(sbase, 2, Ag, Bg, 2, t); cpa_mbar_arrive(mb + 16);

    int pf0 = 0, pf1 = 0, pf2 = 0, pe0 = 0, pe1 = 0, pe2 = 0;
    int it = 0;
    #pragma unroll 1
    for (int blk = 0; blk < 11; blk++) {     // iterations 0..32
        G1_STEP(0, 2, it, pf0, pe2);
        G1_STEP(1, 0, it + 1, pf1, pe0);
        G1_STEP(2, 1, it + 2, pf2, pe1);
        it += 3;
    }
    G1_STEP(0, 2, 33, pf0, pe2);              // tail: iters 33, 34 (no refills)
    G1_STEP(1, 0, 34, pf1, pe0);

    // ---- epilogue: Y fp16 + fused BN1 column stats (dedicated smem region) ----
    float* s_sum = (float*)(sm1 + G1_STATS_OFF);
    float* s_sq = s_sum + 128;
    if (t < 128) { s_sum[t] = 0.f; s_sq[t] = 0.f; }

    #pragma unroll
    for (int mt = 0; mt < 2; mt++) {
        size_t r0 = rowBase + wr * 32 + mt * 16 + g;
        #pragma unroll
        for (int s = 0; s < 8; s++) {
            int cc = colBase + wc * 64 + s * 8 + 2 * tg;
            __half2 h0 = __floats2half2_rn(acc[mt][s][0], acc[mt][s][1]);
            __half2 h1 = __floats2half2_rn(acc[mt][s][2], acc[mt][s][3]);
            *(__half2*)(g_Y + r0 * HID + cc) = h0;
            *(__half2*)(g_Y + (r0 + 8) * HID + cc) = h1;
        }
    }
    __syncthreads();   // zeros visible; all warps past mainloop

    #pragma unroll
    for (int s = 0; s < 8; s++) {
        #pragma unroll
        for (int j = 0; j < 2; j++) {
            float v0 = acc[0][s][j], v1 = acc[0][s][j + 2];
            float v2 = acc[1][s][j], v3 = acc[1][s][j + 2];
            float sv = v0 + v1 + v2 + v3;
            float qv = v0 * v0 + v1 * v1 + v2 * v2 + v3 * v3;
            #pragma unroll
            for (int o = 4; o < 32; o <<= 1) {
                sv += __shfl_xor_sync(0xFFFFFFFFu, sv, o);
                qv += __shfl_xor_sync(0xFFFFFFFFu, qv, o);
            }
            if (g == 0) {
                int cl = wc * 64 + s * 8 + 2 * tg + j;
                atomicAdd(&s_sum[cl], sv);
                atomicAdd(&s_sq[cl], qv);
            }
        }
    }
    __syncthreads();
    if (t < 128) {
        atomicAdd(&g_colsum[colBase + t], s_sum[t]);
        atomicAdd(&g_colsq[colBase + t], s_sq[t]);
    }
}

// ---- GEMM2: out = relu(BN(Y)) @ W2 + b2, 2 CTA/SM; BN1 finalize fused in prologue --
__device__ __forceinline__ uint32_t bn_h2(uint32_t raw, float2 sc, float2 sh) {
    __half2 h = *(__half2*)&raw;
    float2 f = __half22float2(h);
    f.x = fmaxf(f.x * sc.x + sh.x, 0.f);
    f.y = fmaxf(f.y * sc.y + sh.y, 0.f);
    __half2 o = __floats2half2_rn(f.x, f.y);
    return *(uint32_t*)&o;
}

__device__ __forceinline__ void g2_load(uint32_t sbase, int s, const __half* Ag,
                                        int chunk, int t) {
    int k0 = chunk * 32;
    uint32_t aB = sbase + 8192 + s * STAGE2_B;
    uint32_t bB = aB + 10240;
    #pragma unroll
    for (int i = 0; i < 2; i++) {
        int idx = t + i * 256;
        int r = idx >> 2, c = idx & 3;
        cpa16(aB + r * 80 + c * 16, Ag + (size_t)r * HID + k0 + c * 8);
    }
    {
        int r = t >> 2, c = t & 3;
        cpa16(bB + r * 80 + c * 16, g_W2t + (size_t)r * HID + k0 + c * 8);
    }
}

__global__ __launch_bounds__(256, 2) void k_gemm2(const float* __restrict__ bn1g,
                                                  const float* __restrict__ bn1b,
                                                  const float* __restrict__ b2,
                                                  float* __restrict__ out) {
    extern __shared__ char sm2[];
    float* s_scale = (float*)sm2;
    float* s_shift = s_scale + 1024;
    uint32_t sbase = smem_u32(sm2);
    int t = threadIdx.x;
    int warp = t >> 5, lane = t & 31;
    int wr = warp >> 1, wc = warp & 1;
    int g = lane >> 2, tg = lane & 3;
    const size_t rowBase = (size_t)blockIdx.y * 128;
    const __half* Ag = g_Y + rowBase * HID;

    // fused BN1 finalize: scale/shift from column stats
    #pragma unroll
    for (int i = t; i < 1024; i += 256) {
        float m = g_colsum[i] / (float)NR;
        float v = g_colsq[i] / (float)NR - m * m;
        float sc = __ldg(&bn1g[i]) * rsqrtf(v + EPSV);
        s_scale[i] = sc;
        s_shift[i] = __ldg(&bn1b[i]) - m * sc;
    }

    float acc[2][4][4];
    #pragma unroll
    for (int i = 0; i < 2; i++)
        #pragma unroll
        for (int j = 0; j < 4; j++)
            #pragma unroll
            for (int c = 0; c < 4; c++) acc[i][j][c] = 0.f;

    g2_load(sbase, 0, Ag, 0, t); cpa_commit();
    g2_load(sbase, 1, Ag, 1, t); cpa_commit();

    const int NIT = HID / 32;
    for (int it = 0; it < NIT; ++it) {
        cpa_wait1();
        __syncthreads();
        if (it + 2 < NIT) g2_load(sbase, (it + 2) % 3, Ag, it + 2, t);
        cpa_commit();

        const char* aS = sm2 + 8192 + (it % 3) * STAGE2_B;
        const char* bS = aS + 10240;
        #pragma unroll
        for (int kk = 0; kk < 2; kk++) {
            int kloc = kk * 16 + 2 * tg;
            int kglob = it * 32 + kloc;
            float2 sc0 = *(float2*)(s_scale + kglob);
            float2 sh0 = *(float2*)(s_shift + kglob);
            float2 sc1 = *(float2*)(s_scale + kglob + 8);
            float2 sh1 = *(float2*)(s_shift + kglob + 8);
            int kb = kloc * 2;
            uint32_t a[2][4];
            #pragma unroll
            for (int rt = 0; rt < 2; rt++) {
                int r0 = wr * 32 + rt * 16 + g;
                a[rt][0] = bn_h2(*(const uint32_t*)(aS + r0 * 80 + kb), sc0, sh0);
                a[rt][1] = bn_h2(*(const uint32_t*)(aS + (r0 + 8) * 80 + kb), sc0, sh0);
                a[rt][2] = bn_h2(*(const uint32_t*)(aS + r0 * 80 + kb + 16), sc1, sh1);
                a[rt][3] = bn_h2(*(const uint32_t*)(aS + (r0 + 8) * 80 + kb + 16), sc1, sh1);
            }
            #pragma unroll
            for (int s = 0; s < 4; s++) {
                int n = wc * 32 + s * 8 + g;
                uint32_t b0 = *(const uint32_t*)(bS + n * 80 + kb);
                uint32_t b1 = *(const uint32_t*)(bS + n * 80 + kb + 16);
                mma16816(acc[0][s], a[0], b0, b1);
                mma16816(acc[1][s], a[1], b0, b1);
            }
        }
    }

    #pragma unroll
    for (int rt = 0; rt < 2; rt++) {
        size_t r0 = rowBase + wr * 32 + rt * 16 + g;
        #pragma unroll
        for (int s = 0; s < 4; s++) {
            int cc = wc * 32 + s * 8 + 2 * tg;
            if (cc < COUT) {
                float bb = __ldg(&b2[cc]);
                out[r0 * COUT + cc] = acc[rt][s][0] + bb;
                out[(r0 + 8) * COUT + cc] = acc[rt][s][2] + bb;
            }
            if (cc + 1 < COUT) {
                float bb = __ldg(&b2[cc + 1]);
                out[r0 * COUT + cc + 1] = acc[rt][s][1] + bb;
                out[(r0 + 8) * COUT + cc + 1] = acc[rt][s][3] + bb;
            }
        }
    }
}

extern "C" void kernel_launch(void* const* d_in, const int* in_sizes, int n_in,
                              void* d_out, int out_size) {
    const float* dist  = (const float*)d_in[0];
    const float* boxes = (const float*)d_in[1];
    const float* feat  = (const float*)d_in[2];
    const float* objW  = (const float*)d_in[3];
    const float* bn4g  = (const float*)d_in[4];
    const float* bn4b  = (const float*)d_in[5];
    const float* posW  = (const float*)d_in[6];
    const float* posB  = (const float*)d_in[7];
    const float* w1    = (const float*)d_in[8];
    // d_in[9] = dec_b1: cancels inside BatchNorm, unused
    const float* bn1g  = (const float*)d_in[10];
    const float* bn1b  = (const float*)d_in[11];
    const float* w2    = (const float*)d_in[12];
    const float* b2    = (const float*)d_in[13];
    float* out = (float*)d_out;

    cudaFuncSetAttribute(k_gemm1, cudaFuncAttributeMaxDynamicSharedMemorySize, SMEM_G1);
    cudaFuncSetAttribute(k_gemm2, cudaFuncAttributeMaxDynamicSharedMemorySize, SMEM_G2);

    k_bn4_reduce<<<BN4_BLOCKS, 256>>>(boxes);
    k_bn4_fin<<<1, 64>>>(bn4g, bn4b);
    k_pre<<<PRE_GRID, 256>>>(feat, w1, objW, w2, dist, boxes, posW, posB);
    k_gemm1<<<dim3(HID / G1_BN, NR / G1_BM), 256, SMEM_G1>>>();   // 4th launch -> ncu capture
    k_gemm2<<<dim3(1, NR / 128), 256, SMEM_G2>>>(bn1g, bn1b, b2, out);
}